// round 14
// baseline (speedup 1.0000x reference)
#include <cuda_runtime.h>

#define NB 1024
#define NN 64
#define DD 128
#define NE 512
#define BE (NB*NE)
#define HS 132                 // padded smem row stride (float4-aligned)
#define HSZ (NN*HS)            // 8448 floats
#define SIMS_S 76              // 4 pad | 64 data | 8 pad ; 19 quads ≡ 3 (mod 8)
#define P1S 44                 // 4 pad | 32 data | 8 pad ; 11 quads ≡ 3 (mod 8)
#define P1PLANE (32*P1S)       // 1408
#define FEAT_DIM 12288
#define KS4 3072               // FEAT_DIM/4

typedef unsigned long long u64;

__device__ float g_feat[NB*FEAT_DIM];
__device__ float g_hidp[4][NB*512];
__device__ float g_WT[3*16384];   // [l][kb(32)][j(128)][kk(4)] = W_l[kb*4+kk][j]

#define TAIL_WORDS 7040
#define SMEM_WORDS (4*HSZ + TAIL_WORDS)
#define SMEM_BYTES (SMEM_WORDS*4)

// lin: As[2][128][36] + Bs[2][32][72] floats
#define LIN_SMEM_WORDS (2*4608 + 2*2304)
#define LIN_SMEM_BYTES (LIN_SMEM_WORDS*4)

__device__ __forceinline__ float relu(float v) { return fmaxf(v, 0.f); }

__device__ __forceinline__ u64 dup2(float v) {
    u64 r; asm("mov.b64 %0, {%1, %1};" : "=l"(r) : "f"(v)); return r;
}
__device__ __forceinline__ float2 upk(u64 v) {
    float2 r; asm("mov.b64 {%0, %1}, %2;" : "=f"(r.x), "=f"(r.y) : "l"(v)); return r;
}
__device__ __forceinline__ void fma2(u64 &d, u64 a, u64 b) {
    asm("fma.rn.f32x2 %0, %1, %2, %0;" : "+l"(d) : "l"(a), "l"(b));
}
// pair-interleaved row permutations (conflict-free strided access)
__device__ __forceinline__ int srow(int r) { return (r >> 1) + ((r & 1) << 5); }  // 64 rows
__device__ __forceinline__ int prow(int r) { return (r >> 1) + ((r & 1) << 4); }  // 32 rows

// ---- setup: W[l] (k-major) -> g_WT k-quad blocked layout ----
__global__ __launch_bounds__(256)
void transpose_w(const float* __restrict__ w0, const float* __restrict__ w1,
                 const float* __restrict__ w2)
{
    int idx = blockIdx.x * 256 + threadIdx.x;       // 0..49151
    int l = idx >> 14, rem = idx & 16383;
    int k = rem >> 7, j = rem & 127;
    const float* W = (l == 0) ? w0 : (l == 1) ? w1 : w2;
    g_WT[l*16384 + (((k >> 2)*128 + j) << 2) + (k & 3)] = W[k*128 + j];
}

__global__ __launch_bounds__(512, 1)
void fused_kernel(const float* __restrict__ x_q, const float* __restrict__ x_c,
                  const float* __restrict__ b0, const float* __restrict__ b1,
                  const float* __restrict__ b2,
                  const float* __restrict__ c1w, const float* __restrict__ c1b,
                  const float* __restrict__ c2w, const float* __restrict__ c2b,
                  const int* __restrict__ eiq, const int* __restrict__ eic)
{
    extern __shared__ __align__(16) float sm[];
    float* Hq = sm;
    float* Hc = Hq + HSZ;
    float* Mq = Hc + HSZ;
    float* Mc = Mq + HSZ;
    float* sims = Mq;                 // 64*76 = 4864
    float* p1   = Mq + 4864;          // 8*32*44 = 11264
    float* tail = sm + 4*HSZ;
    int*   off_q = (int*)tail;        // 65
    int*   off_c = off_q + 65;        // 65
    int*   cntq  = off_c + 65;        // 64
    int*   cntc  = cntq + 64;         // 64
    int*   curq  = cntc + 64;         // 64
    int*   curc  = curq + 64;         // 64
    int*   csq   = curc + 64;         // 512
    int*   csc   = csq + 512;         // 512
    u64*   cnq2  = (u64*)(csc + 512); // 512 u64
    u64*   cnc2  = cnq2 + 512;        // 512 u64
    float* disq  = (float*)(cnc2 + 512); // 64
    float* disc  = disq + 64;         // 64
    float* w1t   = disc + 64;         // 200  : [(dy*5+dx)*8 + c]
    float* w2t   = w1t + 200;         // 3200 : [((ci*5+dy)*5+dx)*16 + c]

    const int b    = blockIdx.x;
    const int t    = threadIdx.x;
    const int base = b * NN;

    // ---- load node features, vectorized ----
    for (int idx = t; idx < NN*DD/4; idx += 512) {
        int i = idx >> 5, k4 = (idx & 31) * 4;
        *reinterpret_cast<float4*>(&Hq[i*HS + k4]) =
            *reinterpret_cast<const float4*>(&x_q[(base + i)*DD + k4]);
        *reinterpret_cast<float4*>(&Hc[i*HS + k4]) =
            *reinterpret_cast<const float4*>(&x_c[(base + i)*DD + k4]);
    }
    if (t < 64) { cntq[t] = 0; cntc[t] = 0; }
    __syncthreads();

    // ---- edges: degree count; stage packed (s,d) in dead M region ----
    int* tq = (int*)Mq;
    int* tc = (int*)Mc;
    if (t < NE) {
        int e = b*NE + t;
        int s = eiq[e] - base, d = eiq[BE + e] - base;
        tq[t] = (s << 8) | d;
        atomicAdd(&cntq[d], 1);
        s = eic[e] - base; d = eic[BE + e] - base;
        tc[t] = (s << 8) | d;
        atomicAdd(&cntc[d], 1);
    }
    __syncthreads();
    if (t < 64)        disq[t]      = rsqrtf((float)cntq[t] + 1.0f);
    else if (t < 128)  disc[t - 64] = rsqrtf((float)cntc[t - 64] + 1.0f);
    if (t == 0)  { int a = 0; for (int i = 0; i < 64; i++){ off_q[i] = a; a += cntq[i]; } off_q[64] = a; }
    if (t == 32) { int a = 0; for (int i = 0; i < 64; i++){ off_c[i] = a; a += cntc[i]; } off_c[64] = a; }
    __syncthreads();
    if (t < 64) { curq[t] = off_q[t]; curc[t] = off_c[t]; }
    __syncthreads();
    if (t < NE) {
        int sd = tq[t]; int s = sd >> 8, d = sd & 255;
        int p = atomicAdd(&curq[d], 1);
        csq[p] = s; cnq2[p] = dup2(disq[s] * disq[d]);
        sd = tc[t]; s = sd >> 8; d = sd & 255;
        p = atomicAdd(&curc[d], 1);
        csc[p] = s; cnc2[p] = dup2(disc[s] * disc[d]);
    }
    __syncthreads();

    for (int l = 0; l < 3; l++) {
        const float* bb  = (l == 0) ? b0 : (l == 1) ? b1 : b2;
        const float* WTl = g_WT + l*16384;

        // ---- GEMM: M = H @ W, k-packed on WT (zero dups) ----
        {
            const int L  = t & 31;            // column lane: cols L + 32*jj
            const int ig = (t >> 5) * 2;      // warp row base
            #pragma unroll 1
            for (int o = 0; o < 2; o++) {
                const int i0 = ig + o*32;
                u64 aq[2][4] = {}, ac[2][4] = {};
                for (int kb = 0; kb < 32; kb++) {
                    ulonglong2 hq0 = *reinterpret_cast<const ulonglong2*>(&Hq[i0*HS + kb*4]);
                    ulonglong2 hq1 = *reinterpret_cast<const ulonglong2*>(&Hq[(i0+1)*HS + kb*4]);
                    ulonglong2 hc0 = *reinterpret_cast<const ulonglong2*>(&Hc[i0*HS + kb*4]);
                    ulonglong2 hc1 = *reinterpret_cast<const ulonglong2*>(&Hc[(i0+1)*HS + kb*4]);
                    #pragma unroll
                    for (int jj = 0; jj < 4; jj++) {
                        ulonglong2 wt = *reinterpret_cast<const ulonglong2*>(
                            &WTl[((kb*128 + L + 32*jj) << 2)]);
                        fma2(aq[0][jj], hq0.x, wt.x); fma2(aq[0][jj], hq0.y, wt.y);
                        fma2(aq[1][jj], hq1.x, wt.x); fma2(aq[1][jj], hq1.y, wt.y);
                        fma2(ac[0][jj], hc0.x, wt.x); fma2(ac[0][jj], hc0.y, wt.y);
                        fma2(ac[1][jj], hc1.x, wt.x); fma2(ac[1][jj], hc1.y, wt.y);
                    }
                }
                #pragma unroll
                for (int r = 0; r < 2; r++) {
                    #pragma unroll
                    for (int jj = 0; jj < 4; jj++) {
                        float2 vq = upk(aq[r][jj]);
                        float2 vc = upk(ac[r][jj]);
                        Mq[(i0 + r)*HS + L + 32*jj] = vq.x + vq.y;
                        Mc[(i0 + r)*HS + L + 32*jj] = vc.x + vc.y;
                    }
                }
            }
        }
        __syncthreads();

        // ---- aggregate via CSR, feature pairs (u64), pre-dup'd norms ----
        {
            const int f2 = (t & 63) * 2, g = t >> 6;   // g in 0..7
            u64 bf2 = *reinterpret_cast<const u64*>(&bb[f2]);
            #pragma unroll 1
            for (int r = 0; r < 8; r++) {
                int i = g + (r << 3);
                u64 acc = bf2;
                fma2(acc, dup2(disq[i]*disq[i]), *reinterpret_cast<const u64*>(&Mq[i*HS + f2]));
                int e0 = off_q[i], e1 = off_q[i + 1];
                for (int p = e0; p < e1; p++)
                    fma2(acc, cnq2[p], *reinterpret_cast<const u64*>(&Mq[csq[p]*HS + f2]));
                *reinterpret_cast<u64*>(&Hq[i*HS + f2]) = acc;
                acc = bf2;
                fma2(acc, dup2(disc[i]*disc[i]), *reinterpret_cast<const u64*>(&Mc[i*HS + f2]));
                e0 = off_c[i]; e1 = off_c[i + 1];
                for (int p = e0; p < e1; p++)
                    fma2(acc, cnc2[p], *reinterpret_cast<const u64*>(&Mc[csc[p]*HS + f2]));
                *reinterpret_cast<u64*>(&Hc[i*HS + f2]) = acc;
            }
        }
        __syncthreads();

        // ---- sims = out_q @ out_c^T, f32x2 k-packed ; perm-row stores ----
        {
            const int j = t & 31, ig = t >> 5;
            u64 a2[4][2] = {};
            for (int k = 0; k < DD; k += 4) {
                ulonglong2 ca = *reinterpret_cast<const ulonglong2*>(&Hc[j*HS + k]);
                ulonglong2 cb = *reinterpret_cast<const ulonglong2*>(&Hc[(j + 32)*HS + k]);
                #pragma unroll
                for (int r = 0; r < 4; r++) {
                    ulonglong2 qv = *reinterpret_cast<const ulonglong2*>(&Hq[(ig*4 + r)*HS + k]);
                    fma2(a2[r][0], qv.x, ca.x);
                    fma2(a2[r][0], qv.y, ca.y);
                    fma2(a2[r][1], qv.x, cb.x);
                    fma2(a2[r][1], qv.y, cb.y);
                }
            }
            #pragma unroll
            for (int r = 0; r < 4; r++) {
                float2 s0 = upk(a2[r][0]);
                float2 s1 = upk(a2[r][1]);
                int sr = srow(ig*4 + r);
                sims[sr*SIMS_S + 4 + j]      = s0.x + s0.y;
                sims[sr*SIMS_S + 4 + j + 32] = s1.x + s1.y;
            }
        }
        // zero pads: sims (cols 0-3, 68-75), p1 (cols 0-3, 36-43)
        {
            float4 z4 = make_float4(0.f, 0.f, 0.f, 0.f);
            if (t < 64) {
                float* rp = &sims[t*SIMS_S];
                *reinterpret_cast<float4*>(rp)      = z4;
                *reinterpret_cast<float4*>(rp + 68) = z4;
                *reinterpret_cast<float4*>(rp + 72) = z4;
            } else if (t < 320) {
                int s = t - 64;
                float* rp = &p1[(s >> 5)*P1PLANE + (s & 31)*P1S];
                *reinterpret_cast<float4*>(rp)      = z4;
                *reinterpret_cast<float4*>(rp + 36) = z4;
                *reinterpret_cast<float4*>(rp + 40) = z4;
            }
        }
        // stage conv weights, channel-transposed
        for (int idx = t; idx < 200; idx += 512) {
            int c = idx & 7, rest = idx >> 3;
            w1t[idx] = c1w[l*200 + c*25 + rest];
        }
        for (int idx = t; idx < 3200; idx += 512) {
            int c = idx & 15, rest = idx >> 4;
            int dxx = rest % 5, r2 = rest / 5;
            int dyy = r2 % 5, ci = r2 / 5;
            w2t[idx] = c2w[l*3200 + (c*8 + ci)*25 + dyy*5 + dxx];
        }
        __syncthreads();

        // ---- conv1 (1->8,5x5,pad2)+relu+pool2 ; boundary-pruned m-outer ----
        #pragma unroll 1
        for (int it = 0; it < 2; it++) {
            int item = it*512 + t;
            int py = item & 31, xg = (item >> 5) & 7, cp = item >> 8;
            int Xc = xg * 8, Y = py * 2;
            int c0 = cp * 2;
            u64 bias2 = *reinterpret_cast<const u64*>(&c1b[l*8 + c0]);
            u64 A0[8], A1[8];
            #pragma unroll
            for (int j = 0; j < 8; j++) { A0[j] = bias2; A1[j] = bias2; }
            u64 pw[5];
            #pragma unroll
            for (int d = 0; d < 5; d++) pw[d] = 0;
            #pragma unroll
            for (int iy6 = 0; iy6 < 6; iy6++) {
                int iy = Y - 2 + iy6;
                float in[16];
                if ((unsigned)iy < 64u) {
                    const float* rp = &sims[srow(iy)*SIMS_S + Xc];
                    float4 v0 = *reinterpret_cast<const float4*>(rp);
                    float4 v1 = *reinterpret_cast<const float4*>(rp + 4);
                    float4 v2 = *reinterpret_cast<const float4*>(rp + 8);
                    float4 v3 = *reinterpret_cast<const float4*>(rp + 12);
                    in[0]=v0.x; in[1]=v0.y; in[2]=v0.z; in[3]=v0.w;
                    in[4]=v1.x; in[5]=v1.y; in[6]=v1.z; in[7]=v1.w;
                    in[8]=v2.x; in[9]=v2.y; in[10]=v2.z; in[11]=v2.w;
                    in[12]=v3.x; in[13]=v3.y; in[14]=v3.z; in[15]=v3.w;
                } else {
                    #pragma unroll
                    for (int i = 0; i < 16; i++) in[i] = 0.f;
                }
                u64 cw[5];
                #pragma unroll
                for (int d = 0; d < 5; d++)
                    cw[d] = (iy6 < 5)
                        ? *reinterpret_cast<const u64*>(&w1t[(iy6*5 + d)*8 + c0]) : 0ull;
                #pragma unroll
                for (int m = 2; m < 14; m++) {
                    u64 x2 = dup2(in[m]);
                    if (iy6 < 5) {
                        #pragma unroll
                        for (int d = 0; d < 5; d++) {
                            int j = m - d - 2;
                            if (j >= 0 && j < 8) fma2(A0[j], x2, cw[d]);
                        }
                    }
                    if (iy6 >= 1) {
                        #pragma unroll
                        for (int d = 0; d < 5; d++) {
                            int j = m - d - 2;
                            if (j >= 0 && j < 8) fma2(A1[j], x2, pw[d]);
                        }
                    }
                }
                #pragma unroll
                for (int d = 0; d < 5; d++) pw[d] = cw[d];
            }
            float2 q0[8], q1[8];
            #pragma unroll
            for (int j = 0; j < 8; j++) { q0[j] = upk(A0[j]); q1[j] = upk(A1[j]); }
            float4 o0, o1;
            o0.x = relu(fmaxf(fmaxf(q0[0].x,q0[1].x), fmaxf(q1[0].x,q1[1].x)));
            o0.y = relu(fmaxf(fmaxf(q0[2].x,q0[3].x), fmaxf(q1[2].x,q1[3].x)));
            o0.z = relu(fmaxf(fmaxf(q0[4].x,q0[5].x), fmaxf(q1[4].x,q1[5].x)));
            o0.w = relu(fmaxf(fmaxf(q0[6].x,q0[7].x), fmaxf(q1[6].x,q1[7].x)));
            o1.x = relu(fmaxf(fmaxf(q0[0].y,q0[1].y), fmaxf(q1[0].y,q1[1].y)));
            o1.y = relu(fmaxf(fmaxf(q0[2].y,q0[3].y), fmaxf(q1[2].y,q1[3].y)));
            o1.z = relu(fmaxf(fmaxf(q0[4].y,q0[5].y), fmaxf(q1[4].y,q1[5].y)));
            o1.w = relu(fmaxf(fmaxf(q0[6].y,q0[7].y), fmaxf(q1[6].y,q1[7].y)));
            int pr = prow(py);
            *reinterpret_cast<float4*>(&p1[c0*P1PLANE     + pr*P1S + 4 + xg*4]) = o0;
            *reinterpret_cast<float4*>(&p1[(c0+1)*P1PLANE + pr*P1S + 4 + xg*4]) = o1;
        }
        // in-place H = relu(H) for next layer's GEMM
        if (l < 2) {
            #pragma unroll
            for (int p = 0; p < 8; p++) {
                int idx = t + p*512;                 // 0..4095
                float* hp = (idx & 2048) ? Hc : Hq;
                int rem = idx & 2047;
                float* ptr = hp + (rem >> 5)*HS + (rem & 31)*4;
                float4 v = *reinterpret_cast<const float4*>(ptr);
                v.x = relu(v.x); v.y = relu(v.y); v.z = relu(v.z); v.w = relu(v.w);
                *reinterpret_cast<float4*>(ptr) = v;
            }
        }
        __syncthreads();

        // ---- conv2 (8->16,5x5,pad2)+relu+pool2 ; boundary-pruned m-outer ----
        {
            int py = t & 15, xg = (t >> 4) & 3, cp = t >> 6;
            int Xc = xg * 8, Y = py * 2;
            int c0 = cp * 2;
            u64 bias2 = *reinterpret_cast<const u64*>(&c2b[l*16 + c0]);
            u64 A0[8], A1[8];
            #pragma unroll
            for (int j = 0; j < 8; j++) { A0[j] = bias2; A1[j] = bias2; }
            #pragma unroll 1
            for (int ci = 0; ci < 8; ci++) {
                const float* pch = p1 + ci*P1PLANE;
                const float* wch = w2t + ci*400;
                u64 pw[5];
                #pragma unroll
                for (int d = 0; d < 5; d++) pw[d] = 0;
                #pragma unroll
                for (int iy6 = 0; iy6 < 6; iy6++) {
                    int iy = Y - 2 + iy6;
                    float in[16];
                    if ((unsigned)iy < 32u) {
                        const float* rp = pch + prow(iy)*P1S + Xc;
                        float4 v0 = *reinterpret_cast<const float4*>(rp);
                        float4 v1 = *reinterpret_cast<const float4*>(rp + 4);
                        float4 v2 = *reinterpret_cast<const float4*>(rp + 8);
                        float4 v3 = *reinterpret_cast<const float4*>(rp + 12);
                        in[0]=v0.x; in[1]=v0.y; in[2]=v0.z; in[3]=v0.w;
                        in[4]=v1.x; in[5]=v1.y; in[6]=v1.z; in[7]=v1.w;
                        in[8]=v2.x; in[9]=v2.y; in[10]=v2.z; in[11]=v2.w;
                        in[12]=v3.x; in[13]=v3.y; in[14]=v3.z; in[15]=v3.w;
                    } else {
                        #pragma unroll
                        for (int i = 0; i < 16; i++) in[i] = 0.f;
                    }
                    u64 cw[5];
                    #pragma unroll
                    for (int d = 0; d < 5; d++)
                        cw[d] = (iy6 < 5)
                            ? *reinterpret_cast<const u64*>(&wch[(iy6*5 + d)*16 + c0]) : 0ull;
                    #pragma unroll
                    for (int m = 2; m < 14; m++) {
                        u64 x2 = dup2(in[m]);
                        if (iy6 < 5) {
                            #pragma unroll
                            for (int d = 0; d < 5; d++) {
                                int j = m - d - 2;
                                if (j >= 0 && j < 8) fma2(A0[j], x2, cw[d]);
                            }
                        }
                        if (iy6 >= 1) {
                            #pragma unroll
                            for (int d = 0; d < 5; d++) {
                                int j = m - d - 2;
                                if (j >= 0 && j < 8) fma2(A1[j], x2, pw[d]);
                            }
                        }
                    }
                    #pragma unroll
                    for (int d = 0; d < 5; d++) pw[d] = cw[d];
                }
            }
            float2 q0[8], q1[8];
            #pragma unroll
            for (int j = 0; j < 8; j++) { q0[j] = upk(A0[j]); q1[j] = upk(A1[j]); }
            float4 o0, o1;
            o0.x = relu(fmaxf(fmaxf(q0[0].x,q0[1].x), fmaxf(q1[0].x,q1[1].x)));
            o0.y = relu(fmaxf(fmaxf(q0[2].x,q0[3].x), fmaxf(q1[2].x,q1[3].x)));
            o0.z = relu(fmaxf(fmaxf(q0[4].x,q0[5].x), fmaxf(q1[4].x,q1[5].x)));
            o0.w = relu(fmaxf(fmaxf(q0[6].x,q0[7].x), fmaxf(q1[6].x,q1[7].x)));
            o1.x = relu(fmaxf(fmaxf(q0[0].y,q0[1].y), fmaxf(q1[0].y,q1[1].y)));
            o1.y = relu(fmaxf(fmaxf(q0[2].y,q0[3].y), fmaxf(q1[2].y,q1[3].y)));
            o1.z = relu(fmaxf(fmaxf(q0[4].y,q0[5].y), fmaxf(q1[4].y,q1[5].y)));
            o1.w = relu(fmaxf(fmaxf(q0[6].y,q0[7].y), fmaxf(q1[6].y,q1[7].y)));
            *reinterpret_cast<float4*>(
                &g_feat[b*FEAT_DIM + ((l*16 + c0)*16 + py)*16 + xg*4])     = o0;
            *reinterpret_cast<float4*>(
                &g_feat[b*FEAT_DIM + ((l*16 + c0 + 1)*16 + py)*16 + xg*4]) = o1;
        }
        if (l < 2) __syncthreads();
    }
}

// ---- partial = feat @ lin_w (K slice) : double-buffered pipeline ----
__global__ __launch_bounds__(256, 2)
void lin_kernel(const float* __restrict__ Wl)
{
    extern __shared__ __align__(16) float dsm[];
    float* AsBase = dsm;              // [2][128][36]
    float* BsBase = dsm + 2*4608;     // [2][32][72]

    const int blk   = blockIdx.x & 63;
    const int slice = blockIdx.x >> 6;           // 0..3
    const int bn = blk & 7;
    const int bm = blk >> 3;                     // 0..7
    const int t  = threadIdx.x;
    const int tyg = t & 31;
    const int txg = t >> 5;
    const int j0 = txg * 8;
    const int rowBase = bm * 128, colBase = bn * 64;
    const int kBase = slice * KS4;
    float* out = g_hidp[slice];

    const int a_row = t >> 3, a_k4 = (t & 7) * 4;
    const int b_row = t >> 4, b_c4 = (t & 15) * 4;
    const float* gA = &g_feat[(rowBase + a_row)*FEAT_DIM + kBase + a_k4];
    const float* gB = &Wl[(kBase + b_row)*512 + colBase + b_c4];

    float4 ra[4], rb[2];
    #pragma unroll
    for (int r = 0; r < 4; r++)
        ra[r] = *reinterpret_cast<const float4*>(gA + r*32*FEAT_DIM);
    #pragma unroll
    for (int r = 0; r < 2; r++)
        rb[r] = *reinterpret_cast<const float4*>(gB + r*16*512);
    #pragma unroll
    for (int r = 0; r < 4; r++)
        *reinterpret_cast<float4*>(&AsBase[(a_row + r*32)*36 + a_k4]) = ra[r];
    #pragma unroll
    for (int r = 0; r < 2; r++)
        *reinterpret_cast<float4*>(&BsBase[(b_row + r*16)*72 + b_c4]) = rb[r];
    gA += 32; gB += 32*512;
    #pragma unroll
    for (int r = 0; r < 4; r++)
        ra[r] = *reinterpret_cast<const float4*>(gA + r*32*FEAT_DIM);
    #pragma unroll
    for (int r = 0; r < 2; r++)
        rb[r] = *reinterpret_cast<const float4*>(gB + r*16*512);
    gA += 32; gB += 32*512;
    __syncthreads();

    u64 acc2[4][4] = {};
    const int NKT = KS4 / 32;   // 96
    #pragma unroll 1
    for (int it = 0; it < NKT; it++) {
        const float* As = AsBase + (it & 1)*4608;
        const float* Bs = BsBase + (it & 1)*2304;
        #pragma unroll
        for (int k = 0; k < 32; k += 4) {
            float4 av[4];
            #pragma unroll
            for (int m = 0; m < 4; m++)
                av[m] = *reinterpret_cast<const float4*>(&As[(tyg + 32*m)*36 + k]);
            #pragma unroll
            for (int kk = 0; kk < 4; kk++) {
                ulonglong2 bvA = *reinterpret_cast<const ulonglong2*>(&Bs[(k + kk)*72 + j0]);
                ulonglong2 bvB = *reinterpret_cast<const ulonglong2*>(&Bs[(k + kk)*72 + j0 + 4]);
                #pragma unroll
                for (int m = 0; m < 4; m++) {
                    float a = kk == 0 ? av[m].x : kk == 1 ? av[m].y : kk == 2 ? av[m].z : av[m].w;
                    u64 a2 = dup2(a);
                    fma2(acc2[m][0], a2, bvA.x);
                    fma2(acc2[m][1], a2, bvA.y);
                    fma2(acc2[m][2], a2, bvB.x);
                    fma2(acc2[m][3], a2, bvB.y);
                }
            }
        }
        if (it + 1 < NKT) {
            float* Asw = AsBase + ((it + 1) & 1)*4608;
            float* Bsw = BsBase + ((it + 1) & 1)*2304;
            #pragma unroll
            for (int r = 0; r < 4; r++)
                *reinterpret_cast<float4*>(&Asw[(a_row + r*32)*36 + a_k4]) = ra[r];
            #pragma unroll
            for (int r = 0; r < 2; r++)
                *reinterpret_cast<float4*>(&Bsw[(b_row + r*16)*72 + b_c4]) = rb[r];
            if (it + 2 < NKT) {
                #pragma unroll
                for (int r = 0; r < 4; r++)
                    ra[r] = *reinterpret_cast<const float4*>(gA + r*32*FEAT_DIM);
                #pragma unroll
                for (int r = 0; r < 2; r++)
                    rb[r] = *reinterpret_cast<const float4*>(gB + r*16*512);
                gA += 32; gB += 32*512;
            }
        }
        __syncthreads();
    }
    #pragma unroll
    for (int m = 0; m < 4; m++) {
        ulonglong2 sA; sA.x = acc2[m][0]; sA.y = acc2[m][1];
        ulonglong2 sB; sB.x = acc2[m][2]; sB.y = acc2[m][3];
        float* op = &out[(rowBase + tyg + 32*m)*512 + colBase + j0];
        *reinterpret_cast<ulonglong2*>(op)     = sA;
        *reinterpret_cast<ulonglong2*>(op + 4) = sB;
    }
}

// ---- out = relu(sum partials + lin_b) @ score_w + score_b ; float4 loads ----
__global__ __launch_bounds__(256)
void score_kernel(const float* __restrict__ bl,
                  const float* __restrict__ sw, const float* __restrict__ sb,
                  float* __restrict__ out)
{
    int gw   = (blockIdx.x * blockDim.x + threadIdx.x) >> 5;
    int lane = threadIdx.x & 31;
    if (gw >= NB) return;
    const float* h0 = g_hidp[0] + gw * 512;
    const float* h1 = g_hidp[1] + gw * 512;
    const float* h2 = g_hidp[2] + gw * 512;
    const float* h3 = g_hidp[3] + gw * 512;
    float s = 0.f;
    #pragma unroll
    for (int j4 = lane * 4; j4 < 512; j4 += 128) {
        float4 a0 = *reinterpret_cast<const float4*>(h0 + j4);
        float4 a1 = *reinterpret_cast<const float4*>(h1 + j4);
        float4 a2 = *reinterpret_cast<const float4*>(h2 + j4);
        float4 a3 = *reinterpret_cast<const float4*>(h3 + j4);
        float4 bv = *reinterpret_cast<const float4*>(bl + j4);
        float4 wv = *reinterpret_cast<const float4*>(sw + j4);
        s += relu(a0.x + a1.x + a2.x + a3.x + bv.x) * wv.x;
        s += relu(a0.y + a1.y + a2.y + a3.y + bv.y) * wv.y;
        s += relu(a0.z + a1.z + a2.z + a3.z + bv.z) * wv.z;
        s += relu(a0.w + a1.w + a2.w + a3.w + bv.w) * wv.w;
    }
    #pragma unroll
    for (int o = 16; o > 0; o >>= 1) s += __shfl_xor_sync(0xFFFFFFFFu, s, o);
    if (lane == 0) out[gw] = s + sb[0];
}

extern "C" void kernel_launch(void* const* d_in, const int* in_sizes, int n_in,
                              void* d_out, int out_size)
{
    const float* x_q  = (const float*)d_in[0];
    const float* x_c  = (const float*)d_in[1];
    const float* w0   = (const float*)d_in[2];
    const float* b0   = (const float*)d_in[3];
    const float* w1   = (const float*)d_in[4];
    const float* b1   = (const float*)d_in[5];
    const float* w2   = (const float*)d_in[6];
    const float* b2   = (const float*)d_in[7];
    const float* c1w  = (const float*)d_in[8];
    const float* c1b  = (const float*)d_in[9];
    const float* c2w  = (const float*)d_in[10];
    const float* c2b  = (const float*)d_in[11];
    const float* linw = (const float*)d_in[12];
    const float* linb = (const float*)d_in[13];
    const float* scw  = (const float*)d_in[14];
    const float* scb  = (const float*)d_in[15];
    const int*   eiq  = (const int*)d_in[16];
    const int*   eic  = (const int*)d_in[17];

    cudaFuncSetAttribute(fused_kernel, cudaFuncAttributeMaxDynamicSharedMemorySize, SMEM_BYTES);
    cudaFuncSetAttribute(lin_kernel, cudaFuncAttributeMaxDynamicSharedMemorySize, LIN_SMEM_BYTES);

    transpose_w<<<192, 256>>>(w0, w1, w2);
    fused_kernel<<<NB, 512, SMEM_BYTES>>>(x_q, x_c, b0, b1, b2,
                                          c1w, c1b, c2w, c2b, eiq, eic);
    lin_kernel<<<256, 256, LIN_SMEM_BYTES>>>(linw);
    score_kernel<<<128, 256>>>(linb, scw, scb, (float*)d_out);
}

// round 15
// speedup vs baseline: 1.0362x; 1.0362x over previous
#include <cuda_runtime.h>

#define NB 1024
#define NN 64
#define DD 128
#define NE 512
#define BE (NB*NE)
#define HS 132                 // padded smem row stride (float4-aligned)
#define HSZ (NN*HS)            // 8448 floats
#define SIMS_S 76              // 4 pad | 64 data | 8 pad ; 19 quads ≡ 3 (mod 8)
#define P1S 44                 // 4 pad | 32 data | 8 pad ; 11 quads ≡ 3 (mod 8)
#define P1PLANE (32*P1S)       // 1408
#define FEAT_DIM 12288
#define KS4 3072               // FEAT_DIM/4

typedef unsigned long long u64;

__device__ float g_feat[NB*FEAT_DIM];
__device__ float g_hidp[4][NB*512];

#define TAIL_WORDS 13840
#define SMEM_WORDS (4*HSZ + TAIL_WORDS)
#define SMEM_BYTES (SMEM_WORDS*4)

// lin: As[2][128][36] + Bs[2][32][72] floats
#define LIN_SMEM_WORDS (2*4608 + 2*2304)
#define LIN_SMEM_BYTES (LIN_SMEM_WORDS*4)

__device__ __forceinline__ float relu(float v) { return fmaxf(v, 0.f); }

__device__ __forceinline__ u64 dup2(float v) {
    u64 r; asm("mov.b64 %0, {%1, %1};" : "=l"(r) : "f"(v)); return r;
}
__device__ __forceinline__ float2 upk(u64 v) {
    float2 r; asm("mov.b64 {%0, %1}, %2;" : "=f"(r.x), "=f"(r.y) : "l"(v)); return r;
}
__device__ __forceinline__ void fma2(u64 &d, u64 a, u64 b) {
    asm("fma.rn.f32x2 %0, %1, %2, %0;" : "+l"(d) : "l"(a), "l"(b));
}
// pair-interleaved row permutations (conflict-free strided access)
__device__ __forceinline__ int srow(int r) { return (r >> 1) + ((r & 1) << 5); }  // 64 rows
__device__ __forceinline__ int prow(int r) { return (r >> 1) + ((r & 1) << 4); }  // 32 rows

__global__ __launch_bounds__(512, 1)
void fused_kernel(const float* __restrict__ x_q, const float* __restrict__ x_c,
                  const float* __restrict__ w0, const float* __restrict__ b0,
                  const float* __restrict__ w1, const float* __restrict__ b1,
                  const float* __restrict__ w2, const float* __restrict__ b2,
                  const float* __restrict__ c1w, const float* __restrict__ c1b,
                  const float* __restrict__ c2w, const float* __restrict__ c2b,
                  const int* __restrict__ eiq, const int* __restrict__ eic)
{
    extern __shared__ __align__(16) float sm[];
    float* Hq = sm;
    float* Hc = Hq + HSZ;
    float* Mq = Hc + HSZ;
    float* Mc = Mq + HSZ;
    float* sims = Mq;                 // 64*76 = 4864
    float* p1   = Mq + 4864;          // 8*32*44 = 11264
    float* tail = sm + 4*HSZ;
    int*   off_q = (int*)tail;        // 65
    int*   off_c = off_q + 65;        // 65
    int*   cntq  = off_c + 65;        // 64
    int*   cntc  = cntq + 64;         // 64
    int*   curq  = cntc + 64;         // 64
    int*   curc  = curq + 64;         // 64
    int*   csq   = curc + 64;         // 512
    int*   csc   = csq + 512;         // 512
    u64*   cnq2  = (u64*)(csc + 512); // 512 u64
    u64*   cnc2  = cnq2 + 512;        // 512 u64
    float* disq  = (float*)(cnc2 + 512); // 64
    float* disc  = disq + 64;         // 64
    float* w1t   = disc + 64;         // 3*200  : [l][(dy*5+dx)*8 + c]
    float* w2t   = w1t + 600;         // 3*3200 : [l][((ci*5+dy)*5+dx)*16 + c]

    const int b    = blockIdx.x;
    const int t    = threadIdx.x;
    const int base = b * NN;

    // ---- load node features, vectorized ----
    for (int idx = t; idx < NN*DD/4; idx += 512) {
        int i = idx >> 5, k4 = (idx & 31) * 4;
        *reinterpret_cast<float4*>(&Hq[i*HS + k4]) =
            *reinterpret_cast<const float4*>(&x_q[(base + i)*DD + k4]);
        *reinterpret_cast<float4*>(&Hc[i*HS + k4]) =
            *reinterpret_cast<const float4*>(&x_c[(base + i)*DD + k4]);
    }
    if (t < 64) { cntq[t] = 0; cntc[t] = 0; }
    // ---- stage ALL conv weights once (channel-transposed) ----
    for (int idx = t; idx < 600; idx += 512) {
        int l = idx / 200, within = idx % 200;
        int c = within & 7, rest = within >> 3;
        w1t[idx] = c1w[l*200 + c*25 + rest];
    }
    for (int idx = t; idx < 9600; idx += 512) {
        int l = idx / 3200, within = idx % 3200;
        int c = within & 15, rest = within >> 4;
        int dxx = rest % 5, r2 = rest / 5;
        int dyy = r2 % 5, ci = r2 / 5;
        w2t[idx] = c2w[l*3200 + (c*8 + ci)*25 + dyy*5 + dxx];
    }
    __syncthreads();

    // ---- edges: degree count; stage packed (s,d) in dead M region ----
    int* tq = (int*)Mq;
    int* tc = (int*)Mc;
    if (t < NE) {
        int e = b*NE + t;
        int s = eiq[e] - base, d = eiq[BE + e] - base;
        tq[t] = (s << 8) | d;
        atomicAdd(&cntq[d], 1);
        s = eic[e] - base; d = eic[BE + e] - base;
        tc[t] = (s << 8) | d;
        atomicAdd(&cntc[d], 1);
    }
    __syncthreads();
    if (t < 64)        disq[t]      = rsqrtf((float)cntq[t] + 1.0f);
    else if (t < 128)  disc[t - 64] = rsqrtf((float)cntc[t - 64] + 1.0f);
    if (t == 0)  { int a = 0; for (int i = 0; i < 64; i++){ off_q[i] = a; a += cntq[i]; } off_q[64] = a; }
    if (t == 32) { int a = 0; for (int i = 0; i < 64; i++){ off_c[i] = a; a += cntc[i]; } off_c[64] = a; }
    __syncthreads();
    if (t < 64) { curq[t] = off_q[t]; curc[t] = off_c[t]; }
    __syncthreads();
    if (t < NE) {
        int sd = tq[t]; int s = sd >> 8, d = sd & 255;
        int p = atomicAdd(&curq[d], 1);
        csq[p] = s; cnq2[p] = dup2(disq[s] * disq[d]);
        sd = tc[t]; s = sd >> 8; d = sd & 255;
        p = atomicAdd(&curc[d], 1);
        csc[p] = s; cnc2[p] = dup2(disc[s] * disc[d]);
    }
    __syncthreads();

    for (int l = 0; l < 3; l++) {
        const float* W  = (l == 0) ? w0 : (l == 1) ? w1 : w2;
        const float* bb = (l == 0) ? b0 : (l == 1) ? b1 : b2;
        const float* w1l = w1t + l*200;
        const float* w2l = w2t + l*3200;

        // ---- GEMM: M = H @ W (H already relu'd in place for l>0) ----
        {
            const int j0 = (t & 31) * 4, i0 = (t >> 5) * 4;
            u64 aq2[4][2] = {}, ac2[4][2] = {};
            for (int k = 0; k < DD; k += 4) {
                float4 hq[4], hc[4];
                #pragma unroll
                for (int r = 0; r < 4; r++) {
                    hq[r] = *reinterpret_cast<const float4*>(&Hq[(i0 + r)*HS + k]);
                    hc[r] = *reinterpret_cast<const float4*>(&Hc[(i0 + r)*HS + k]);
                }
                #pragma unroll
                for (int kk = 0; kk < 4; kk++) {
                    ulonglong2 wv = *reinterpret_cast<const ulonglong2*>(W + (k + kk)*DD + j0);
                    #pragma unroll
                    for (int r = 0; r < 4; r++) {
                        float aqv = kk == 0 ? hq[r].x : kk == 1 ? hq[r].y : kk == 2 ? hq[r].z : hq[r].w;
                        u64 ad = dup2(aqv);
                        fma2(aq2[r][0], ad, wv.x);
                        fma2(aq2[r][1], ad, wv.y);
                        float acv = kk == 0 ? hc[r].x : kk == 1 ? hc[r].y : kk == 2 ? hc[r].z : hc[r].w;
                        u64 cd = dup2(acv);
                        fma2(ac2[r][0], cd, wv.x);
                        fma2(ac2[r][1], cd, wv.y);
                    }
                }
            }
            #pragma unroll
            for (int r = 0; r < 4; r++) {
                ulonglong2 sq; sq.x = aq2[r][0]; sq.y = aq2[r][1];
                ulonglong2 sc; sc.x = ac2[r][0]; sc.y = ac2[r][1];
                *reinterpret_cast<ulonglong2*>(&Mq[(i0 + r)*HS + j0]) = sq;
                *reinterpret_cast<ulonglong2*>(&Mc[(i0 + r)*HS + j0]) = sc;
            }
        }
        __syncthreads();

        // ---- aggregate via CSR, feature pairs (u64), pre-dup'd norms ----
        {
            const int f2 = (t & 63) * 2, g = t >> 6;   // g in 0..7
            u64 bf2 = *reinterpret_cast<const u64*>(&bb[f2]);
            #pragma unroll 1
            for (int r = 0; r < 8; r++) {
                int i = g + (r << 3);
                u64 acc = bf2;
                fma2(acc, dup2(disq[i]*disq[i]), *reinterpret_cast<const u64*>(&Mq[i*HS + f2]));
                int e0 = off_q[i], e1 = off_q[i + 1];
                for (int p = e0; p < e1; p++)
                    fma2(acc, cnq2[p], *reinterpret_cast<const u64*>(&Mq[csq[p]*HS + f2]));
                *reinterpret_cast<u64*>(&Hq[i*HS + f2]) = acc;
                acc = bf2;
                fma2(acc, dup2(disc[i]*disc[i]), *reinterpret_cast<const u64*>(&Mc[i*HS + f2]));
                e0 = off_c[i]; e1 = off_c[i + 1];
                for (int p = e0; p < e1; p++)
                    fma2(acc, cnc2[p], *reinterpret_cast<const u64*>(&Mc[csc[p]*HS + f2]));
                *reinterpret_cast<u64*>(&Hc[i*HS + f2]) = acc;
            }
        }
        __syncthreads();

        // ---- sims = out_q @ out_c^T, f32x2 k-packed ; perm-row stores ----
        {
            const int j = t & 31, ig = t >> 5;
            u64 a2[4][2] = {};
            for (int k = 0; k < DD; k += 4) {
                ulonglong2 ca = *reinterpret_cast<const ulonglong2*>(&Hc[j*HS + k]);
                ulonglong2 cb = *reinterpret_cast<const ulonglong2*>(&Hc[(j + 32)*HS + k]);
                #pragma unroll
                for (int r = 0; r < 4; r++) {
                    ulonglong2 qv = *reinterpret_cast<const ulonglong2*>(&Hq[(ig*4 + r)*HS + k]);
                    fma2(a2[r][0], qv.x, ca.x);
                    fma2(a2[r][0], qv.y, ca.y);
                    fma2(a2[r][1], qv.x, cb.x);
                    fma2(a2[r][1], qv.y, cb.y);
                }
            }
            #pragma unroll
            for (int r = 0; r < 4; r++) {
                float2 s0 = upk(a2[r][0]);
                float2 s1 = upk(a2[r][1]);
                int sr = srow(ig*4 + r);
                sims[sr*SIMS_S + 4 + j]      = s0.x + s0.y;
                sims[sr*SIMS_S + 4 + j + 32] = s1.x + s1.y;
            }
        }
        // zero pads: sims (cols 0-3, 68-75), p1 (cols 0-3, 36-43)
        {
            float4 z4 = make_float4(0.f, 0.f, 0.f, 0.f);
            if (t < 64) {
                float* rp = &sims[t*SIMS_S];
                *reinterpret_cast<float4*>(rp)      = z4;
                *reinterpret_cast<float4*>(rp + 68) = z4;
                *reinterpret_cast<float4*>(rp + 72) = z4;
            } else if (t < 320) {
                int s = t - 64;
                float* rp = &p1[(s >> 5)*P1PLANE + (s & 31)*P1S];
                *reinterpret_cast<float4*>(rp)      = z4;
                *reinterpret_cast<float4*>(rp + 36) = z4;
                *reinterpret_cast<float4*>(rp + 40) = z4;
            }
        }
        __syncthreads();

        // ---- conv1 (1->8,5x5,pad2)+relu+pool2 ; boundary-pruned m-outer ----
        #pragma unroll 1
        for (int it = 0; it < 2; it++) {
            int item = it*512 + t;
            int py = item & 31, xg = (item >> 5) & 7, cp = item >> 8;
            int Xc = xg * 8, Y = py * 2;
            int c0 = cp * 2;
            u64 bias2 = *reinterpret_cast<const u64*>(&c1b[l*8 + c0]);
            u64 A0[8], A1[8];
            #pragma unroll
            for (int j = 0; j < 8; j++) { A0[j] = bias2; A1[j] = bias2; }
            u64 pw[5];
            #pragma unroll
            for (int d = 0; d < 5; d++) pw[d] = 0;
            #pragma unroll
            for (int iy6 = 0; iy6 < 6; iy6++) {
                int iy = Y - 2 + iy6;
                float in[16];
                if ((unsigned)iy < 64u) {
                    const float* rp = &sims[srow(iy)*SIMS_S + Xc];
                    float4 v0 = *reinterpret_cast<const float4*>(rp);
                    float4 v1 = *reinterpret_cast<const float4*>(rp + 4);
                    float4 v2 = *reinterpret_cast<const float4*>(rp + 8);
                    float4 v3 = *reinterpret_cast<const float4*>(rp + 12);
                    in[0]=v0.x; in[1]=v0.y; in[2]=v0.z; in[3]=v0.w;
                    in[4]=v1.x; in[5]=v1.y; in[6]=v1.z; in[7]=v1.w;
                    in[8]=v2.x; in[9]=v2.y; in[10]=v2.z; in[11]=v2.w;
                    in[12]=v3.x; in[13]=v3.y; in[14]=v3.z; in[15]=v3.w;
                } else {
                    #pragma unroll
                    for (int i = 0; i < 16; i++) in[i] = 0.f;
                }
                u64 cw[5];
                #pragma unroll
                for (int d = 0; d < 5; d++)
                    cw[d] = (iy6 < 5)
                        ? *reinterpret_cast<const u64*>(&w1l[(iy6*5 + d)*8 + c0]) : 0ull;
                #pragma unroll
                for (int m = 2; m < 14; m++) {
                    u64 x2 = dup2(in[m]);
                    if (iy6 < 5) {
                        #pragma unroll
                        for (int d = 0; d < 5; d++) {
                            int j = m - d - 2;
                            if (j >= 0 && j < 8) fma2(A0[j], x2, cw[d]);
                        }
                    }
                    if (iy6 >= 1) {
                        #pragma unroll
                        for (int d = 0; d < 5; d++) {
                            int j = m - d - 2;
                            if (j >= 0 && j < 8) fma2(A1[j], x2, pw[d]);
                        }
                    }
                }
                #pragma unroll
                for (int d = 0; d < 5; d++) pw[d] = cw[d];
            }
            float2 q0[8], q1[8];
            #pragma unroll
            for (int j = 0; j < 8; j++) { q0[j] = upk(A0[j]); q1[j] = upk(A1[j]); }
            float4 o0, o1;
            o0.x = relu(fmaxf(fmaxf(q0[0].x,q0[1].x), fmaxf(q1[0].x,q1[1].x)));
            o0.y = relu(fmaxf(fmaxf(q0[2].x,q0[3].x), fmaxf(q1[2].x,q1[3].x)));
            o0.z = relu(fmaxf(fmaxf(q0[4].x,q0[5].x), fmaxf(q1[4].x,q1[5].x)));
            o0.w = relu(fmaxf(fmaxf(q0[6].x,q0[7].x), fmaxf(q1[6].x,q1[7].x)));
            o1.x = relu(fmaxf(fmaxf(q0[0].y,q0[1].y), fmaxf(q1[0].y,q1[1].y)));
            o1.y = relu(fmaxf(fmaxf(q0[2].y,q0[3].y), fmaxf(q1[2].y,q1[3].y)));
            o1.z = relu(fmaxf(fmaxf(q0[4].y,q0[5].y), fmaxf(q1[4].y,q1[5].y)));
            o1.w = relu(fmaxf(fmaxf(q0[6].y,q0[7].y), fmaxf(q1[6].y,q1[7].y)));
            int pr = prow(py);
            *reinterpret_cast<float4*>(&p1[c0*P1PLANE     + pr*P1S + 4 + xg*4]) = o0;
            *reinterpret_cast<float4*>(&p1[(c0+1)*P1PLANE + pr*P1S + 4 + xg*4]) = o1;
        }
        // in-place H = relu(H) for next layer's GEMM
        if (l < 2) {
            #pragma unroll
            for (int p = 0; p < 8; p++) {
                int idx = t + p*512;                 // 0..4095
                float* hp = (idx & 2048) ? Hc : Hq;
                int rem = idx & 2047;
                float* ptr = hp + (rem >> 5)*HS + (rem & 31)*4;
                float4 v = *reinterpret_cast<const float4*>(ptr);
                v.x = relu(v.x); v.y = relu(v.y); v.z = relu(v.z); v.w = relu(v.w);
                *reinterpret_cast<float4*>(ptr) = v;
            }
        }
        __syncthreads();

        // ---- conv2 (8->16,5x5,pad2)+relu+pool2 ; boundary-pruned m-outer ----
        {
            int py = t & 15, xg = (t >> 4) & 3, cp = t >> 6;
            int Xc = xg * 8, Y = py * 2;
            int c0 = cp * 2;
            u64 bias2 = *reinterpret_cast<const u64*>(&c2b[l*16 + c0]);
            u64 A0[8], A1[8];
            #pragma unroll
            for (int j = 0; j < 8; j++) { A0[j] = bias2; A1[j] = bias2; }
            #pragma unroll 1
            for (int ci = 0; ci < 8; ci++) {
                const float* pch = p1 + ci*P1PLANE;
                const float* wch = w2l + ci*400;
                u64 pw[5];
                #pragma unroll
                for (int d = 0; d < 5; d++) pw[d] = 0;
                #pragma unroll
                for (int iy6 = 0; iy6 < 6; iy6++) {
                    int iy = Y - 2 + iy6;
                    float in[16];
                    if ((unsigned)iy < 32u) {
                        const float* rp = pch + prow(iy)*P1S + Xc;
                        float4 v0 = *reinterpret_cast<const float4*>(rp);
                        float4 v1 = *reinterpret_cast<const float4*>(rp + 4);
                        float4 v2 = *reinterpret_cast<const float4*>(rp + 8);
                        float4 v3 = *reinterpret_cast<const float4*>(rp + 12);
                        in[0]=v0.x; in[1]=v0.y; in[2]=v0.z; in[3]=v0.w;
                        in[4]=v1.x; in[5]=v1.y; in[6]=v1.z; in[7]=v1.w;
                        in[8]=v2.x; in[9]=v2.y; in[10]=v2.z; in[11]=v2.w;
                        in[12]=v3.x; in[13]=v3.y; in[14]=v3.z; in[15]=v3.w;
                    } else {
                        #pragma unroll
                        for (int i = 0; i < 16; i++) in[i] = 0.f;
                    }
                    u64 cw[5];
                    #pragma unroll
                    for (int d = 0; d < 5; d++)
                        cw[d] = (iy6 < 5)
                            ? *reinterpret_cast<const u64*>(&wch[(iy6*5 + d)*16 + c0]) : 0ull;
                    #pragma unroll
                    for (int m = 2; m < 14; m++) {
                        u64 x2 = dup2(in[m]);
                        if (iy6 < 5) {
                            #pragma unroll
                            for (int d = 0; d < 5; d++) {
                                int j = m - d - 2;
                                if (j >= 0 && j < 8) fma2(A0[j], x2, cw[d]);
                            }
                        }
                        if (iy6 >= 1) {
                            #pragma unroll
                            for (int d = 0; d < 5; d++) {
                                int j = m - d - 2;
                                if (j >= 0 && j < 8) fma2(A1[j], x2, pw[d]);
                            }
                        }
                    }
                    #pragma unroll
                    for (int d = 0; d < 5; d++) pw[d] = cw[d];
                }
            }
            float2 q0[8], q1[8];
            #pragma unroll
            for (int j = 0; j < 8; j++) { q0[j] = upk(A0[j]); q1[j] = upk(A1[j]); }
            float4 o0, o1;
            o0.x = relu(fmaxf(fmaxf(q0[0].x,q0[1].x), fmaxf(q1[0].x,q1[1].x)));
            o0.y = relu(fmaxf(fmaxf(q0[2].x,q0[3].x), fmaxf(q1[2].x,q1[3].x)));
            o0.z = relu(fmaxf(fmaxf(q0[4].x,q0[5].x), fmaxf(q1[4].x,q1[5].x)));
            o0.w = relu(fmaxf(fmaxf(q0[6].x,q0[7].x), fmaxf(q1[6].x,q1[7].x)));
            o1.x = relu(fmaxf(fmaxf(q0[0].y,q0[1].y), fmaxf(q1[0].y,q1[1].y)));
            o1.y = relu(fmaxf(fmaxf(q0[2].y,q0[3].y), fmaxf(q1[2].y,q1[3].y)));
            o1.z = relu(fmaxf(fmaxf(q0[4].y,q0[5].y), fmaxf(q1[4].y,q1[5].y)));
            o1.w = relu(fmaxf(fmaxf(q0[6].y,q0[7].y), fmaxf(q1[6].y,q1[7].y)));
            *reinterpret_cast<float4*>(
                &g_feat[b*FEAT_DIM + ((l*16 + c0)*16 + py)*16 + xg*4])     = o0;
            *reinterpret_cast<float4*>(
                &g_feat[b*FEAT_DIM + ((l*16 + c0 + 1)*16 + py)*16 + xg*4]) = o1;
        }
        if (l < 2) __syncthreads();
    }
}

// ---- partial = feat @ lin_w (K slice) : double-buffered pipeline ----
__global__ __launch_bounds__(256, 2)
void lin_kernel(const float* __restrict__ Wl)
{
    extern __shared__ __align__(16) float dsm[];
    float* AsBase = dsm;              // [2][128][36]
    float* BsBase = dsm + 2*4608;     // [2][32][72]

    const int blk   = blockIdx.x & 63;
    const int slice = blockIdx.x >> 6;           // 0..3
    const int bn = blk & 7;
    const int bm = blk >> 3;                     // 0..7
    const int t  = threadIdx.x;
    const int tyg = t & 31;
    const int txg = t >> 5;
    const int j0 = txg * 8;
    const int rowBase = bm * 128, colBase = bn * 64;
    const int kBase = slice * KS4;
    float* out = g_hidp[slice];

    const int a_row = t >> 3, a_k4 = (t & 7) * 4;
    const int b_row = t >> 4, b_c4 = (t & 15) * 4;
    const float* gA = &g_feat[(rowBase + a_row)*FEAT_DIM + kBase + a_k4];
    const float* gB = &Wl[(kBase + b_row)*512 + colBase + b_c4];

    float4 ra[4], rb[2];
    #pragma unroll
    for (int r = 0; r < 4; r++)
        ra[r] = *reinterpret_cast<const float4*>(gA + r*32*FEAT_DIM);
    #pragma unroll
    for (int r = 0; r < 2; r++)
        rb[r] = *reinterpret_cast<const float4*>(gB + r*16*512);
    #pragma unroll
    for (int r = 0; r < 4; r++)
        *reinterpret_cast<float4*>(&AsBase[(a_row + r*32)*36 + a_k4]) = ra[r];
    #pragma unroll
    for (int r = 0; r < 2; r++)
        *reinterpret_cast<float4*>(&BsBase[(b_row + r*16)*72 + b_c4]) = rb[r];
    gA += 32; gB += 32*512;
    #pragma unroll
    for (int r = 0; r < 4; r++)
        ra[r] = *reinterpret_cast<const float4*>(gA + r*32*FEAT_DIM);
    #pragma unroll
    for (int r = 0; r < 2; r++)
        rb[r] = *reinterpret_cast<const float4*>(gB + r*16*512);
    gA += 32; gB += 32*512;
    __syncthreads();

    u64 acc2[4][4] = {};
    const int NKT = KS4 / 32;   // 96
    #pragma unroll 1
    for (int it = 0; it < NKT; it++) {
        const float* As = AsBase + (it & 1)*4608;
        const float* Bs = BsBase + (it & 1)*2304;
        #pragma unroll
        for (int k = 0; k < 32; k += 4) {
            float4 av[4];
            #pragma unroll
            for (int m = 0; m < 4; m++)
                av[m] = *reinterpret_cast<const float4*>(&As[(tyg + 32*m)*36 + k]);
            #pragma unroll
            for (int kk = 0; kk < 4; kk++) {
                ulonglong2 bvA = *reinterpret_cast<const ulonglong2*>(&Bs[(k + kk)*72 + j0]);
                ulonglong2 bvB = *reinterpret_cast<const ulonglong2*>(&Bs[(k + kk)*72 + j0 + 4]);
                #pragma unroll
                for (int m = 0; m < 4; m++) {
                    float a = kk == 0 ? av[m].x : kk == 1 ? av[m].y : kk == 2 ? av[m].z : av[m].w;
                    u64 a2 = dup2(a);
                    fma2(acc2[m][0], a2, bvA.x);
                    fma2(acc2[m][1], a2, bvA.y);
                    fma2(acc2[m][2], a2, bvB.x);
                    fma2(acc2[m][3], a2, bvB.y);
                }
            }
        }
        if (it + 1 < NKT) {
            float* Asw = AsBase + ((it + 1) & 1)*4608;
            float* Bsw = BsBase + ((it + 1) & 1)*2304;
            #pragma unroll
            for (int r = 0; r < 4; r++)
                *reinterpret_cast<float4*>(&Asw[(a_row + r*32)*36 + a_k4]) = ra[r];
            #pragma unroll
            for (int r = 0; r < 2; r++)
                *reinterpret_cast<float4*>(&Bsw[(b_row + r*16)*72 + b_c4]) = rb[r];
            if (it + 2 < NKT) {
                #pragma unroll
                for (int r = 0; r < 4; r++)
                    ra[r] = *reinterpret_cast<const float4*>(gA + r*32*FEAT_DIM);
                #pragma unroll
                for (int r = 0; r < 2; r++)
                    rb[r] = *reinterpret_cast<const float4*>(gB + r*16*512);
                gA += 32; gB += 32*512;
            }
        }
        __syncthreads();
    }
    #pragma unroll
    for (int m = 0; m < 4; m++) {
        ulonglong2 sA; sA.x = acc2[m][0]; sA.y = acc2[m][1];
        ulonglong2 sB; sB.x = acc2[m][2]; sB.y = acc2[m][3];
        float* op = &out[(rowBase + tyg + 32*m)*512 + colBase + j0];
        *reinterpret_cast<ulonglong2*>(op)     = sA;
        *reinterpret_cast<ulonglong2*>(op + 4) = sB;
    }
}

// ---- out = relu(sum partials + lin_b) @ score_w + score_b ; float4 loads ----
__global__ __launch_bounds__(256)
void score_kernel(const float* __restrict__ bl,
                  const float* __restrict__ sw, const float* __restrict__ sb,
                  float* __restrict__ out)
{
    int gw   = (blockIdx.x * blockDim.x + threadIdx.x) >> 5;
    int lane = threadIdx.x & 31;
    if (gw >= NB) return;
    const float* h0 = g_hidp[0] + gw * 512;
    const float* h1 = g_hidp[1] + gw * 512;
    const float* h2 = g_hidp[2] + gw * 512;
    const float* h3 = g_hidp[3] + gw * 512;
    float s = 0.f;
    #pragma unroll
    for (int j4 = lane * 4; j4 < 512; j4 += 128) {
        float4 a0 = *reinterpret_cast<const float4*>(h0 + j4);
        float4 a1 = *reinterpret_cast<const float4*>(h1 + j4);
        float4 a2 = *reinterpret_cast<const float4*>(h2 + j4);
        float4 a3 = *reinterpret_cast<const float4*>(h3 + j4);
        float4 bv = *reinterpret_cast<const float4*>(bl + j4);
        float4 wv = *reinterpret_cast<const float4*>(sw + j4);
        s += relu(a0.x + a1.x + a2.x + a3.x + bv.x) * wv.x;
        s += relu(a0.y + a1.y + a2.y + a3.y + bv.y) * wv.y;
        s += relu(a0.z + a1.z + a2.z + a3.z + bv.z) * wv.z;
        s += relu(a0.w + a1.w + a2.w + a3.w + bv.w) * wv.w;
    }
    #pragma unroll
    for (int o = 16; o > 0; o >>= 1) s += __shfl_xor_sync(0xFFFFFFFFu, s, o);
    if (lane == 0) out[gw] = s + sb[0];
}

extern "C" void kernel_launch(void* const* d_in, const int* in_sizes, int n_in,
                              void* d_out, int out_size)
{
    const float* x_q  = (const float*)d_in[0];
    const float* x_c  = (const float*)d_in[1];
    const float* w0   = (const float*)d_in[2];
    const float* b0   = (const float*)d_in[3];
    const float* w1   = (const float*)d_in[4];
    const float* b1   = (const float*)d_in[5];
    const float* w2   = (const float*)d_in[6];
    const float* b2   = (const float*)d_in[7];
    const float* c1w  = (const float*)d_in[8];
    const float* c1b  = (const float*)d_in[9];
    const float* c2w  = (const float*)d_in[10];
    const float* c2b  = (const float*)d_in[11];
    const float* linw = (const float*)d_in[12];
    const float* linb = (const float*)d_in[13];
    const float* scw  = (const float*)d_in[14];
    const float* scb  = (const float*)d_in[15];
    const int*   eiq  = (const int*)d_in[16];
    const int*   eic  = (const int*)d_in[17];

    cudaFuncSetAttribute(fused_kernel, cudaFuncAttributeMaxDynamicSharedMemorySize, SMEM_BYTES);
    cudaFuncSetAttribute(lin_kernel, cudaFuncAttributeMaxDynamicSharedMemorySize, LIN_SMEM_BYTES);

    fused_kernel<<<NB, 512, SMEM_BYTES>>>(x_q, x_c, w0, b0, w1, b1, w2, b2,
                                          c1w, c1b, c2w, c2b, eiq, eic);
    lin_kernel<<<256, 256, LIN_SMEM_BYTES>>>(linw);
    score_kernel<<<128, 256>>>(linb, scw, scb, (float*)d_out);
}

// round 16
// speedup vs baseline: 1.0392x; 1.0029x over previous
#include <cuda_runtime.h>

#define NB 1024
#define NN 64
#define DD 128
#define NE 512
#define BE (NB*NE)
#define HS 132                 // padded smem row stride (float4-aligned)
#define HSZ (NN*HS)            // 8448 floats
#define SIMS_S 76              // 4 pad | 64 data | 8 pad ; 19 quads ≡ 3 (mod 8)
#define P1S 44                 // 4 pad | 32 data | 8 pad ; 11 quads ≡ 3 (mod 8)
#define P1PLANE (32*P1S)       // 1408
#define FEAT_DIM 12288
#define KS4 3072               // FEAT_DIM/4

typedef unsigned long long u64;

__device__ float g_feat[NB*FEAT_DIM];
__device__ float g_hidp[4][NB*512];

#define TAIL_WORDS 7040
#define SMEM_WORDS (4*HSZ + TAIL_WORDS)
#define SMEM_BYTES (SMEM_WORDS*4)

// lin: As[2][128][36] + Bs[2][32][72] floats
#define LIN_SMEM_WORDS (2*4608 + 2*2304)
#define LIN_SMEM_BYTES (LIN_SMEM_WORDS*4)

__device__ __forceinline__ float relu(float v) { return fmaxf(v, 0.f); }

__device__ __forceinline__ u64 dup2(float v) {
    u64 r; asm("mov.b64 %0, {%1, %1};" : "=l"(r) : "f"(v)); return r;
}
__device__ __forceinline__ float2 upk(u64 v) {
    float2 r; asm("mov.b64 {%0, %1}, %2;" : "=f"(r.x), "=f"(r.y) : "l"(v)); return r;
}
__device__ __forceinline__ void fma2(u64 &d, u64 a, u64 b) {
    asm("fma.rn.f32x2 %0, %1, %2, %0;" : "+l"(d) : "l"(a), "l"(b));
}
// pair-interleaved row permutations (conflict-free strided access)
__device__ __forceinline__ int srow(int r) { return (r >> 1) + ((r & 1) << 5); }  // 64 rows
__device__ __forceinline__ int prow(int r) { return (r >> 1) + ((r & 1) << 4); }  // 32 rows

__global__ __launch_bounds__(512, 1)
void fused_kernel(const float* __restrict__ x_q, const float* __restrict__ x_c,
                  const float* __restrict__ w0, const float* __restrict__ b0,
                  const float* __restrict__ w1, const float* __restrict__ b1,
                  const float* __restrict__ w2, const float* __restrict__ b2,
                  const float* __restrict__ c1w, const float* __restrict__ c1b,
                  const float* __restrict__ c2w, const float* __restrict__ c2b,
                  const int* __restrict__ eiq, const int* __restrict__ eic)
{
    extern __shared__ __align__(16) float sm[];
    float* Hq = sm;
    float* Hc = Hq + HSZ;
    float* Mq = Hc + HSZ;
    float* Mc = Mq + HSZ;
    float* sims = Mq;                 // 64*76 = 4864
    float* p1   = Mq + 4864;          // 8*32*44 = 11264
    float* tail = sm + 4*HSZ;
    int*   off_q = (int*)tail;        // 65
    int*   off_c = off_q + 65;        // 65
    int*   cntq  = off_c + 65;        // 64
    int*   cntc  = cntq + 64;         // 64
    int*   curq  = cntc + 64;         // 64
    int*   curc  = curq + 64;         // 64
    int*   csq   = curc + 64;         // 512
    int*   csc   = csq + 512;         // 512
    u64*   cnq2  = (u64*)(csc + 512); // 512 u64
    u64*   cnc2  = cnq2 + 512;        // 512 u64
    float* disq  = (float*)(cnc2 + 512); // 64
    float* disc  = disq + 64;         // 64
    float* w1t   = disc + 64;         // 200  : [(dy*5+dx)*8 + c]
    float* w2t   = w1t + 200;         // 3200 : [((ci*5+dy)*5+dx)*16 + c]

    const int b    = blockIdx.x;
    const int t    = threadIdx.x;
    const int base = b * NN;

    // ---- load node features, vectorized ----
    for (int idx = t; idx < NN*DD/4; idx += 512) {
        int i = idx >> 5, k4 = (idx & 31) * 4;
        *reinterpret_cast<float4*>(&Hq[i*HS + k4]) =
            *reinterpret_cast<const float4*>(&x_q[(base + i)*DD + k4]);
        *reinterpret_cast<float4*>(&Hc[i*HS + k4]) =
            *reinterpret_cast<const float4*>(&x_c[(base + i)*DD + k4]);
    }
    if (t < 64) { cntq[t] = 0; cntc[t] = 0; }
    __syncthreads();

    // ---- edges: degree count; stage packed (s,d) in dead M region ----
    int* tq = (int*)Mq;
    int* tc = (int*)Mc;
    if (t < NE) {
        int e = b*NE + t;
        int s = eiq[e] - base, d = eiq[BE + e] - base;
        tq[t] = (s << 8) | d;
        atomicAdd(&cntq[d], 1);
        s = eic[e] - base; d = eic[BE + e] - base;
        tc[t] = (s << 8) | d;
        atomicAdd(&cntc[d], 1);
    }
    __syncthreads();
    if (t < 64)        disq[t]      = rsqrtf((float)cntq[t] + 1.0f);
    else if (t < 128)  disc[t - 64] = rsqrtf((float)cntc[t - 64] + 1.0f);
    if (t == 0)  { int a = 0; for (int i = 0; i < 64; i++){ off_q[i] = a; a += cntq[i]; } off_q[64] = a; }
    if (t == 32) { int a = 0; for (int i = 0; i < 64; i++){ off_c[i] = a; a += cntc[i]; } off_c[64] = a; }
    __syncthreads();
    if (t < 64) { curq[t] = off_q[t]; curc[t] = off_c[t]; }
    __syncthreads();
    if (t < NE) {
        int sd = tq[t]; int s = sd >> 8, d = sd & 255;
        int p = atomicAdd(&curq[d], 1);
        csq[p] = s; cnq2[p] = dup2(disq[s] * disq[d]);
        sd = tc[t]; s = sd >> 8; d = sd & 255;
        p = atomicAdd(&curc[d], 1);
        csc[p] = s; cnc2[p] = dup2(disc[s] * disc[d]);
    }
    __syncthreads();

    for (int l = 0; l < 3; l++) {
        const float* W  = (l == 0) ? w0 : (l == 1) ? w1 : w2;
        const float* bb = (l == 0) ? b0 : (l == 1) ? b1 : b2;

        // ---- GEMM: M = H @ W (H already relu'd in place for l>0) ----
        {
            const int j0 = (t & 31) * 4, i0 = (t >> 5) * 4;
            u64 aq2[4][2] = {}, ac2[4][2] = {};
            for (int k = 0; k < DD; k += 4) {
                float4 hq[4], hc[4];
                #pragma unroll
                for (int r = 0; r < 4; r++) {
                    hq[r] = *reinterpret_cast<const float4*>(&Hq[(i0 + r)*HS + k]);
                    hc[r] = *reinterpret_cast<const float4*>(&Hc[(i0 + r)*HS + k]);
                }
                #pragma unroll
                for (int kk = 0; kk < 4; kk++) {
                    ulonglong2 wv = *reinterpret_cast<const ulonglong2*>(W + (k + kk)*DD + j0);
                    #pragma unroll
                    for (int r = 0; r < 4; r++) {
                        float aqv = kk == 0 ? hq[r].x : kk == 1 ? hq[r].y : kk == 2 ? hq[r].z : hq[r].w;
                        u64 ad = dup2(aqv);
                        fma2(aq2[r][0], ad, wv.x);
                        fma2(aq2[r][1], ad, wv.y);
                        float acv = kk == 0 ? hc[r].x : kk == 1 ? hc[r].y : kk == 2 ? hc[r].z : hc[r].w;
                        u64 cd = dup2(acv);
                        fma2(ac2[r][0], cd, wv.x);
                        fma2(ac2[r][1], cd, wv.y);
                    }
                }
            }
            #pragma unroll
            for (int r = 0; r < 4; r++) {
                ulonglong2 sq; sq.x = aq2[r][0]; sq.y = aq2[r][1];
                ulonglong2 sc; sc.x = ac2[r][0]; sc.y = ac2[r][1];
                *reinterpret_cast<ulonglong2*>(&Mq[(i0 + r)*HS + j0]) = sq;
                *reinterpret_cast<ulonglong2*>(&Mc[(i0 + r)*HS + j0]) = sc;
            }
        }
        __syncthreads();

        // ---- aggregate via CSR, feature pairs (u64), pre-dup'd norms ----
        {
            const int f2 = (t & 63) * 2, g = t >> 6;   // g in 0..7
            u64 bf2 = *reinterpret_cast<const u64*>(&bb[f2]);
            #pragma unroll 1
            for (int r = 0; r < 8; r++) {
                int i = g + (r << 3);
                u64 acc = bf2;
                fma2(acc, dup2(disq[i]*disq[i]), *reinterpret_cast<const u64*>(&Mq[i*HS + f2]));
                int e0 = off_q[i], e1 = off_q[i + 1];
                for (int p = e0; p < e1; p++)
                    fma2(acc, cnq2[p], *reinterpret_cast<const u64*>(&Mq[csq[p]*HS + f2]));
                *reinterpret_cast<u64*>(&Hq[i*HS + f2]) = acc;
                acc = bf2;
                fma2(acc, dup2(disc[i]*disc[i]), *reinterpret_cast<const u64*>(&Mc[i*HS + f2]));
                e0 = off_c[i]; e1 = off_c[i + 1];
                for (int p = e0; p < e1; p++)
                    fma2(acc, cnc2[p], *reinterpret_cast<const u64*>(&Mc[csc[p]*HS + f2]));
                *reinterpret_cast<u64*>(&Hc[i*HS + f2]) = acc;
            }
        }
        __syncthreads();

        // ---- sims = out_q @ out_c^T, f32x2 k-packed ; perm-row stores ----
        {
            const int j = t & 31, ig = t >> 5;
            u64 a2[4][2] = {};
            for (int k = 0; k < DD; k += 4) {
                ulonglong2 ca = *reinterpret_cast<const ulonglong2*>(&Hc[j*HS + k]);
                ulonglong2 cb = *reinterpret_cast<const ulonglong2*>(&Hc[(j + 32)*HS + k]);
                #pragma unroll
                for (int r = 0; r < 4; r++) {
                    ulonglong2 qv = *reinterpret_cast<const ulonglong2*>(&Hq[(ig*4 + r)*HS + k]);
                    fma2(a2[r][0], qv.x, ca.x);
                    fma2(a2[r][0], qv.y, ca.y);
                    fma2(a2[r][1], qv.x, cb.x);
                    fma2(a2[r][1], qv.y, cb.y);
                }
            }
            #pragma unroll
            for (int r = 0; r < 4; r++) {
                float2 s0 = upk(a2[r][0]);
                float2 s1 = upk(a2[r][1]);
                int sr = srow(ig*4 + r);
                sims[sr*SIMS_S + 4 + j]      = s0.x + s0.y;
                sims[sr*SIMS_S + 4 + j + 32] = s1.x + s1.y;
            }
        }
        // zero pads: sims (cols 0-3, 68-75), p1 (cols 0-3, 36-43)
        {
            float4 z4 = make_float4(0.f, 0.f, 0.f, 0.f);
            if (t < 64) {
                float* rp = &sims[t*SIMS_S];
                *reinterpret_cast<float4*>(rp)      = z4;
                *reinterpret_cast<float4*>(rp + 68) = z4;
                *reinterpret_cast<float4*>(rp + 72) = z4;
            } else if (t < 320) {
                int s = t - 64;
                float* rp = &p1[(s >> 5)*P1PLANE + (s & 31)*P1S];
                *reinterpret_cast<float4*>(rp)      = z4;
                *reinterpret_cast<float4*>(rp + 36) = z4;
                *reinterpret_cast<float4*>(rp + 40) = z4;
            }
        }
        // stage conv weights, channel-transposed
        for (int idx = t; idx < 200; idx += 512) {
            int c = idx & 7, rest = idx >> 3;
            w1t[idx] = c1w[l*200 + c*25 + rest];
        }
        for (int idx = t; idx < 3200; idx += 512) {
            int c = idx & 15, rest = idx >> 4;
            int dxx = rest % 5, r2 = rest / 5;
            int dyy = r2 % 5, ci = r2 / 5;
            w2t[idx] = c2w[l*3200 + (c*8 + ci)*25 + dyy*5 + dxx];
        }
        __syncthreads();

        // ---- conv1 (1->8,5x5,pad2)+relu+pool2 ; boundary-pruned m-outer ----
        #pragma unroll 1
        for (int it = 0; it < 2; it++) {
            int item = it*512 + t;
            int py = item & 31, xg = (item >> 5) & 7, cp = item >> 8;
            int Xc = xg * 8, Y = py * 2;
            int c0 = cp * 2;
            u64 bias2 = *reinterpret_cast<const u64*>(&c1b[l*8 + c0]);
            u64 A0[8], A1[8];
            #pragma unroll
            for (int j = 0; j < 8; j++) { A0[j] = bias2; A1[j] = bias2; }
            u64 pw[5];
            #pragma unroll
            for (int d = 0; d < 5; d++) pw[d] = 0;
            #pragma unroll
            for (int iy6 = 0; iy6 < 6; iy6++) {
                int iy = Y - 2 + iy6;
                float in[16];
                if ((unsigned)iy < 64u) {
                    const float* rp = &sims[srow(iy)*SIMS_S + Xc];
                    float4 v0 = *reinterpret_cast<const float4*>(rp);
                    float4 v1 = *reinterpret_cast<const float4*>(rp + 4);
                    float4 v2 = *reinterpret_cast<const float4*>(rp + 8);
                    float4 v3 = *reinterpret_cast<const float4*>(rp + 12);
                    in[0]=v0.x; in[1]=v0.y; in[2]=v0.z; in[3]=v0.w;
                    in[4]=v1.x; in[5]=v1.y; in[6]=v1.z; in[7]=v1.w;
                    in[8]=v2.x; in[9]=v2.y; in[10]=v2.z; in[11]=v2.w;
                    in[12]=v3.x; in[13]=v3.y; in[14]=v3.z; in[15]=v3.w;
                } else {
                    #pragma unroll
                    for (int i = 0; i < 16; i++) in[i] = 0.f;
                }
                u64 cw[5];
                #pragma unroll
                for (int d = 0; d < 5; d++)
                    cw[d] = (iy6 < 5)
                        ? *reinterpret_cast<const u64*>(&w1t[(iy6*5 + d)*8 + c0]) : 0ull;
                #pragma unroll
                for (int m = 2; m < 14; m++) {
                    u64 x2 = dup2(in[m]);
                    if (iy6 < 5) {
                        #pragma unroll
                        for (int d = 0; d < 5; d++) {
                            int j = m - d - 2;
                            if (j >= 0 && j < 8) fma2(A0[j], x2, cw[d]);
                        }
                    }
                    if (iy6 >= 1) {
                        #pragma unroll
                        for (int d = 0; d < 5; d++) {
                            int j = m - d - 2;
                            if (j >= 0 && j < 8) fma2(A1[j], x2, pw[d]);
                        }
                    }
                }
                #pragma unroll
                for (int d = 0; d < 5; d++) pw[d] = cw[d];
            }
            float2 q0[8], q1[8];
            #pragma unroll
            for (int j = 0; j < 8; j++) { q0[j] = upk(A0[j]); q1[j] = upk(A1[j]); }
            float4 o0, o1;
            o0.x = relu(fmaxf(fmaxf(q0[0].x,q0[1].x), fmaxf(q1[0].x,q1[1].x)));
            o0.y = relu(fmaxf(fmaxf(q0[2].x,q0[3].x), fmaxf(q1[2].x,q1[3].x)));
            o0.z = relu(fmaxf(fmaxf(q0[4].x,q0[5].x), fmaxf(q1[4].x,q1[5].x)));
            o0.w = relu(fmaxf(fmaxf(q0[6].x,q0[7].x), fmaxf(q1[6].x,q1[7].x)));
            o1.x = relu(fmaxf(fmaxf(q0[0].y,q0[1].y), fmaxf(q1[0].y,q1[1].y)));
            o1.y = relu(fmaxf(fmaxf(q0[2].y,q0[3].y), fmaxf(q1[2].y,q1[3].y)));
            o1.z = relu(fmaxf(fmaxf(q0[4].y,q0[5].y), fmaxf(q1[4].y,q1[5].y)));
            o1.w = relu(fmaxf(fmaxf(q0[6].y,q0[7].y), fmaxf(q1[6].y,q1[7].y)));
            int pr = prow(py);
            *reinterpret_cast<float4*>(&p1[c0*P1PLANE     + pr*P1S + 4 + xg*4]) = o0;
            *reinterpret_cast<float4*>(&p1[(c0+1)*P1PLANE + pr*P1S + 4 + xg*4]) = o1;
        }
        // in-place H = relu(H) for next layer's GEMM
        if (l < 2) {
            #pragma unroll
            for (int p = 0; p < 8; p++) {
                int idx = t + p*512;                 // 0..4095
                float* hp = (idx & 2048) ? Hc : Hq;
                int rem = idx & 2047;
                float* ptr = hp + (rem >> 5)*HS + (rem & 31)*4;
                float4 v = *reinterpret_cast<const float4*>(ptr);
                v.x = relu(v.x); v.y = relu(v.y); v.z = relu(v.z); v.w = relu(v.w);
                *reinterpret_cast<float4*>(ptr) = v;
            }
        }
        __syncthreads();

        // ---- conv2 (8->16,5x5,pad2)+relu+pool2 ; boundary-pruned m-outer ----
        {
            int py = t & 15, xg = (t >> 4) & 3, cp = t >> 6;
            int Xc = xg * 8, Y = py * 2;
            int c0 = cp * 2;
            u64 bias2 = *reinterpret_cast<const u64*>(&c2b[l*16 + c0]);
            u64 A0[8], A1[8];
            #pragma unroll
            for (int j = 0; j < 8; j++) { A0[j] = bias2; A1[j] = bias2; }
            #pragma unroll 1
            for (int ci = 0; ci < 8; ci++) {
                const float* pch = p1 + ci*P1PLANE;
                const float* wch = w2t + ci*400;
                u64 pw[5];
                #pragma unroll
                for (int d = 0; d < 5; d++) pw[d] = 0;
                #pragma unroll
                for (int iy6 = 0; iy6 < 6; iy6++) {
                    int iy = Y - 2 + iy6;
                    float in[16];
                    if ((unsigned)iy < 32u) {
                        const float* rp = pch + prow(iy)*P1S + Xc;
                        float4 v0 = *reinterpret_cast<const float4*>(rp);
                        float4 v1 = *reinterpret_cast<const float4*>(rp + 4);
                        float4 v2 = *reinterpret_cast<const float4*>(rp + 8);
                        float4 v3 = *reinterpret_cast<const float4*>(rp + 12);
                        in[0]=v0.x; in[1]=v0.y; in[2]=v0.z; in[3]=v0.w;
                        in[4]=v1.x; in[5]=v1.y; in[6]=v1.z; in[7]=v1.w;
                        in[8]=v2.x; in[9]=v2.y; in[10]=v2.z; in[11]=v2.w;
                        in[12]=v3.x; in[13]=v3.y; in[14]=v3.z; in[15]=v3.w;
                    } else {
                        #pragma unroll
                        for (int i = 0; i < 16; i++) in[i] = 0.f;
                    }
                    u64 cw[5];
                    #pragma unroll
                    for (int d = 0; d < 5; d++)
                        cw[d] = (iy6 < 5)
                            ? *reinterpret_cast<const u64*>(&wch[(iy6*5 + d)*16 + c0]) : 0ull;
                    #pragma unroll
                    for (int m = 2; m < 14; m++) {
                        u64 x2 = dup2(in[m]);
                        if (iy6 < 5) {
                            #pragma unroll
                            for (int d = 0; d < 5; d++) {
                                int j = m - d - 2;
                                if (j >= 0 && j < 8) fma2(A0[j], x2, cw[d]);
                            }
                        }
                        if (iy6 >= 1) {
                            #pragma unroll
                            for (int d = 0; d < 5; d++) {
                                int j = m - d - 2;
                                if (j >= 0 && j < 8) fma2(A1[j], x2, pw[d]);
                            }
                        }
                    }
                    #pragma unroll
                    for (int d = 0; d < 5; d++) pw[d] = cw[d];
                }
            }
            float2 q0[8], q1[8];
            #pragma unroll
            for (int j = 0; j < 8; j++) { q0[j] = upk(A0[j]); q1[j] = upk(A1[j]); }
            float4 o0, o1;
            o0.x = relu(fmaxf(fmaxf(q0[0].x,q0[1].x), fmaxf(q1[0].x,q1[1].x)));
            o0.y = relu(fmaxf(fmaxf(q0[2].x,q0[3].x), fmaxf(q1[2].x,q1[3].x)));
            o0.z = relu(fmaxf(fmaxf(q0[4].x,q0[5].x), fmaxf(q1[4].x,q1[5].x)));
            o0.w = relu(fmaxf(fmaxf(q0[6].x,q0[7].x), fmaxf(q1[6].x,q1[7].x)));
            o1.x = relu(fmaxf(fmaxf(q0[0].y,q0[1].y), fmaxf(q1[0].y,q1[1].y)));
            o1.y = relu(fmaxf(fmaxf(q0[2].y,q0[3].y), fmaxf(q1[2].y,q1[3].y)));
            o1.z = relu(fmaxf(fmaxf(q0[4].y,q0[5].y), fmaxf(q1[4].y,q1[5].y)));
            o1.w = relu(fmaxf(fmaxf(q0[6].y,q0[7].y), fmaxf(q1[6].y,q1[7].y)));
            *reinterpret_cast<float4*>(
                &g_feat[b*FEAT_DIM + ((l*16 + c0)*16 + py)*16 + xg*4])     = o0;
            *reinterpret_cast<float4*>(
                &g_feat[b*FEAT_DIM + ((l*16 + c0 + 1)*16 + py)*16 + xg*4]) = o1;
        }
        if (l < 2) __syncthreads();
    }
}

// ---- partial = feat @ lin_w (K slice) : double-buffered pipeline ----
__global__ __launch_bounds__(256, 2)
void lin_kernel(const float* __restrict__ Wl)
{
    extern __shared__ __align__(16) float dsm[];
    float* AsBase = dsm;              // [2][128][36]
    float* BsBase = dsm + 2*4608;     // [2][32][72]

    const int blk   = blockIdx.x & 63;
    const int slice = blockIdx.x >> 6;           // 0..3
    const int bn = blk & 7;
    const int bm = blk >> 3;                     // 0..7
    const int t  = threadIdx.x;
    const int tyg = t & 31;
    const int txg = t >> 5;
    const int j0 = txg * 8;
    const int rowBase = bm * 128, colBase = bn * 64;
    const int kBase = slice * KS4;
    float* out = g_hidp[slice];

    const int a_row = t >> 3, a_k4 = (t & 7) * 4;
    const int b_row = t >> 4, b_c4 = (t & 15) * 4;
    const float* gA = &g_feat[(rowBase + a_row)*FEAT_DIM + kBase + a_k4];
    const float* gB = &Wl[(kBase + b_row)*512 + colBase + b_c4];

    float4 ra[4], rb[2];
    #pragma unroll
    for (int r = 0; r < 4; r++)
        ra[r] = *reinterpret_cast<const float4*>(gA + r*32*FEAT_DIM);
    #pragma unroll
    for (int r = 0; r < 2; r++)
        rb[r] = *reinterpret_cast<const float4*>(gB + r*16*512);
    #pragma unroll
    for (int r = 0; r < 4; r++)
        *reinterpret_cast<float4*>(&AsBase[(a_row + r*32)*36 + a_k4]) = ra[r];
    #pragma unroll
    for (int r = 0; r < 2; r++)
        *reinterpret_cast<float4*>(&BsBase[(b_row + r*16)*72 + b_c4]) = rb[r];
    gA += 32; gB += 32*512;
    #pragma unroll
    for (int r = 0; r < 4; r++)
        ra[r] = *reinterpret_cast<const float4*>(gA + r*32*FEAT_DIM);
    #pragma unroll
    for (int r = 0; r < 2; r++)
        rb[r] = *reinterpret_cast<const float4*>(gB + r*16*512);
    gA += 32; gB += 32*512;
    __syncthreads();

    u64 acc2[4][4] = {};
    const int NKT = KS4 / 32;   // 96
    #pragma unroll 1
    for (int it = 0; it < NKT; it++) {
        const float* As = AsBase + (it & 1)*4608;
        const float* Bs = BsBase + (it & 1)*2304;
        #pragma unroll
        for (int k = 0; k < 32; k += 4) {
            float4 av[4];
            #pragma unroll
            for (int m = 0; m < 4; m++)
                av[m] = *reinterpret_cast<const float4*>(&As[(tyg + 32*m)*36 + k]);
            #pragma unroll
            for (int kk = 0; kk < 4; kk++) {
                ulonglong2 bvA = *reinterpret_cast<const ulonglong2*>(&Bs[(k + kk)*72 + j0]);
                ulonglong2 bvB = *reinterpret_cast<const ulonglong2*>(&Bs[(k + kk)*72 + j0 + 4]);
                #pragma unroll
                for (int m = 0; m < 4; m++) {
                    float a = kk == 0 ? av[m].x : kk == 1 ? av[m].y : kk == 2 ? av[m].z : av[m].w;
                    u64 a2 = dup2(a);
                    fma2(acc2[m][0], a2, bvA.x);
                    fma2(acc2[m][1], a2, bvA.y);
                    fma2(acc2[m][2], a2, bvB.x);
                    fma2(acc2[m][3], a2, bvB.y);
                }
            }
        }
        if (it + 1 < NKT) {
            float* Asw = AsBase + ((it + 1) & 1)*4608;
            float* Bsw = BsBase + ((it + 1) & 1)*2304;
            #pragma unroll
            for (int r = 0; r < 4; r++)
                *reinterpret_cast<float4*>(&Asw[(a_row + r*32)*36 + a_k4]) = ra[r];
            #pragma unroll
            for (int r = 0; r < 2; r++)
                *reinterpret_cast<float4*>(&Bsw[(b_row + r*16)*72 + b_c4]) = rb[r];
            if (it + 2 < NKT) {
                #pragma unroll
                for (int r = 0; r < 4; r++)
                    ra[r] = *reinterpret_cast<const float4*>(gA + r*32*FEAT_DIM);
                #pragma unroll
                for (int r = 0; r < 2; r++)
                    rb[r] = *reinterpret_cast<const float4*>(gB + r*16*512);
                gA += 32; gB += 32*512;
            }
        }
        __syncthreads();
    }
    #pragma unroll
    for (int m = 0; m < 4; m++) {
        ulonglong2 sA; sA.x = acc2[m][0]; sA.y = acc2[m][1];
        ulonglong2 sB; sB.x = acc2[m][2]; sB.y = acc2[m][3];
        float* op = &out[(rowBase + tyg + 32*m)*512 + colBase + j0];
        *reinterpret_cast<ulonglong2*>(op)     = sA;
        *reinterpret_cast<ulonglong2*>(op + 4) = sB;
    }
}

// ---- out = relu(sum partials + lin_b) @ score_w + score_b ; float4 loads ----
__global__ __launch_bounds__(256)
void score_kernel(const float* __restrict__ bl,
                  const float* __restrict__ sw, const float* __restrict__ sb,
                  float* __restrict__ out)
{
    int gw   = (blockIdx.x * blockDim.x + threadIdx.x) >> 5;
    int lane = threadIdx.x & 31;
    if (gw >= NB) return;
    const float* h0 = g_hidp[0] + gw * 512;
    const float* h1 = g_hidp[1] + gw * 512;
    const float* h2 = g_hidp[2] + gw * 512;
    const float* h3 = g_hidp[3] + gw * 512;
    float s = 0.f;
    #pragma unroll
    for (int j4 = lane * 4; j4 < 512; j4 += 128) {
        float4 a0 = *reinterpret_cast<const float4*>(h0 + j4);
        float4 a1 = *reinterpret_cast<const float4*>(h1 + j4);
        float4 a2 = *reinterpret_cast<const float4*>(h2 + j4);
        float4 a3 = *reinterpret_cast<const float4*>(h3 + j4);
        float4 bv = *reinterpret_cast<const float4*>(bl + j4);
        float4 wv = *reinterpret_cast<const float4*>(sw + j4);
        s += relu(a0.x + a1.x + a2.x + a3.x + bv.x) * wv.x;
        s += relu(a0.y + a1.y + a2.y + a3.y + bv.y) * wv.y;
        s += relu(a0.z + a1.z + a2.z + a3.z + bv.z) * wv.z;
        s += relu(a0.w + a1.w + a2.w + a3.w + bv.w) * wv.w;
    }
    #pragma unroll
    for (int o = 16; o > 0; o >>= 1) s += __shfl_xor_sync(0xFFFFFFFFu, s, o);
    if (lane == 0) out[gw] = s + sb[0];
}

extern "C" void kernel_launch(void* const* d_in, const int* in_sizes, int n_in,
                              void* d_out, int out_size)
{
    const float* x_q  = (const float*)d_in[0];
    const float* x_c  = (const float*)d_in[1];
    const float* w0   = (const float*)d_in[2];
    const float* b0   = (const float*)d_in[3];
    const float* w1   = (const float*)d_in[4];
    const float* b1   = (const float*)d_in[5];
    const float* w2   = (const float*)d_in[6];
    const float* b2   = (const float*)d_in[7];
    const float* c1w  = (const float*)d_in[8];
    const float* c1b  = (const float*)d_in[9];
    const float* c2w  = (const float*)d_in[10];
    const float* c2b  = (const float*)d_in[11];
    const float* linw = (const float*)d_in[12];
    const float* linb = (const float*)d_in[13];
    const float* scw  = (const float*)d_in[14];
    const float* scb  = (const float*)d_in[15];
    const int*   eiq  = (const int*)d_in[16];
    const int*   eic  = (const int*)d_in[17];

    cudaFuncSetAttribute(fused_kernel, cudaFuncAttributeMaxDynamicSharedMemorySize, SMEM_BYTES);
    cudaFuncSetAttribute(lin_kernel, cudaFuncAttributeMaxDynamicSharedMemorySize, LIN_SMEM_BYTES);

    fused_kernel<<<NB, 512, SMEM_BYTES>>>(x_q, x_c, w0, b0, w1, b1, w2, b2,
                                          c1w, c1b, c2w, c2b, eiq, eic);
    lin_kernel<<<256, 256, LIN_SMEM_BYTES>>>(linw);
    score_kernel<<<128, 256>>>(linb, scw, scb, (float*)d_out);
}